// round 8
// baseline (speedup 1.0000x reference)
#include <cuda_runtime.h>

// OMul: r[i] = outer(x[i], y[i]) flattened.
// x: [N, 256] f32, y: [N, 256] f32, out: [N, 65536] f32. 1 GiB of stores.
//
// R8: champion R2 store pattern (.cs float4, warp-uniform smem broadcast,
// 512B contiguous per warp per iteration), but TWO CTAs per row — grid 8192,
// each CTA writes a contiguous 128KB half-row. Finer wave granularity
// smooths the partial-tail wave and halves the per-quantum prologue shadow.

static constexpr int M = 256;
static constexpr int K = 256;
static constexpr int THREADS = 256;
static constexpr int HALF_M = M / 2;   // 128 m-rows per CTA

__global__ __launch_bounds__(THREADS, 8)
void omul_kernel(const float* __restrict__ x,
                 const float* __restrict__ y,
                 float* __restrict__ out)
{
    __shared__ float sx[HALF_M];
    __shared__ float sy[K];

    const int row  = blockIdx.x >> 1;        // source row
    const int half = blockIdx.x & 1;         // which m half
    const int t    = threadIdx.x;

    if (t < HALF_M)
        sx[t] = x[(size_t)row * M + half * HALF_M + t];
    sy[t] = y[(size_t)row * K + t];
    __syncthreads();

    const int k4 = t & 63;        // float4 chunk of k (0..63)
    const int m0 = t >> 6;        // 0..3: m offset within group of 4

    const float4 y4 = reinterpret_cast<const float4*>(sy)[k4];

    float4* out4 = reinterpret_cast<float4*>(
        out + (size_t)row * (M * K) + (size_t)half * HALF_M * K);

    #pragma unroll 8
    for (int mi = 0; mi < HALF_M / 4; mi++) {   // 32 iterations
        const int m = m0 + mi * 4;
        const float xv = sx[m];     // warp-uniform smem broadcast
        float4 v;
        v.x = xv * y4.x;
        v.y = xv * y4.y;
        v.z = xv * y4.z;
        v.w = xv * y4.w;
        // streaming store: output never re-read, full 128B sector coverage
        __stcs(&out4[(size_t)m * 64 + k4], v);
    }
}

extern "C" void kernel_launch(void* const* d_in, const int* in_sizes, int n_in,
                              void* d_out, int out_size)
{
    const float* x = (const float*)d_in[0];
    const float* y = (const float*)d_in[1];
    float* out = (float*)d_out;

    const int n = in_sizes[0] / M;   // 4096 rows

    omul_kernel<<<n * 2, THREADS>>>(x, y, out);
}

// round 9
// speedup vs baseline: 1.3210x; 1.3210x over previous
#include <cuda_runtime.h>

// OMul: r[i] = outer(x[i], y[i]) flattened.
// x: [N, 256] f32, y: [N, 256] f32, out: [N, 65536] f32.
// Pure HBM-write-bound: 1 GiB of .cs streaming stores.
//
// R9: exact R2 champion (grid=4096, 1 row/CTA, smem-staged inputs,
// warp-uniform LDS broadcast, 512B contiguous per warp per iteration,
// __stcs float4 stores) with the 64-iteration store loop FULLY unrolled:
// removes loop overhead and lets ptxas batch LDS ahead of the STG stream.
// Measured ledger: all shape/cache-op/width/TMA deviations regress; DRAM
// plateaus at ~81% (6.45 TB/s) across 4 independent store paths = ceiling.

static constexpr int M = 256;
static constexpr int K = 256;
static constexpr int THREADS = 256;

__global__ __launch_bounds__(THREADS, 8)
void omul_kernel(const float* __restrict__ x,
                 const float* __restrict__ y,
                 float* __restrict__ out)
{
    __shared__ float sx[M];
    __shared__ float sy[K];

    const int row = blockIdx.x;
    const int t   = threadIdx.x;

    sx[t] = x[(size_t)row * M + t];
    sy[t] = y[(size_t)row * K + t];
    __syncthreads();

    const int k4 = t & 63;        // which float4 chunk of k (0..63)
    const int m0 = t >> 6;        // 0..3: m offset within group of 4

    const float4 y4 = reinterpret_cast<const float4*>(sy)[k4];

    float4* out4 = reinterpret_cast<float4*>(out + (size_t)row * (M * K));

    #pragma unroll
    for (int mi = 0; mi < 64; mi++) {
        const int m = m0 + mi * 4;
        const float xv = sx[m];     // warp-uniform broadcast
        float4 v;
        v.x = xv * y4.x;
        v.y = xv * y4.y;
        v.z = xv * y4.z;
        v.w = xv * y4.w;
        // streaming store: output never re-read, full 128B sector coverage
        __stcs(&out4[(size_t)m * 64 + k4], v);
    }
}

extern "C" void kernel_launch(void* const* d_in, const int* in_sizes, int n_in,
                              void* d_out, int out_size)
{
    const float* x = (const float*)d_in[0];
    const float* y = (const float*)d_in[1];
    float* out = (float*)d_out;

    const int n = in_sizes[0] / M;   // 4096 rows

    omul_kernel<<<n, THREADS>>>(x, y, out);
}